// round 10
// baseline (speedup 1.0000x reference)
#include <cuda_runtime.h>
#include <cuda_bf16.h>
#include <cstdint>

#define N_NODES 100000
#define N_EDGES 800000
#define DIM 128
#define NTILES ((N_NODES + 127) / 128)

// ---------------------------------------------------------------------------
// Scratch (allocation-free rule: __device__ globals)
// ---------------------------------------------------------------------------
__device__ float g_v[N_NODES * DIM];
__device__ float g_h[N_NODES * DIM];
__device__ unsigned short g_Wmma[4][2 * 128 * 128];  // prepacked W images

// swizzled byte offset of (row, 16B-chunk kc) in a 256B-row tile
#define SW_OFF(row, kc) ((uint32_t)(row) * 256u + ((uint32_t)(((kc) ^ ((row) & 7))) << 4))

__device__ __forceinline__ uint32_t smem_u32(const void* p) {
    uint32_t a;
    asm("{ .reg .u64 t; cvta.to.shared.u64 t, %1; cvt.u32.u64 %0, t; }"
        : "=r"(a) : "l"(p));
    return a;
}
__device__ __forceinline__ void ldsm_x4(uint32_t& r0, uint32_t& r1, uint32_t& r2,
                                        uint32_t& r3, uint32_t addr) {
    asm volatile("ldmatrix.sync.aligned.m8n8.x4.shared.b16 {%0,%1,%2,%3}, [%4];"
                 : "=r"(r0), "=r"(r1), "=r"(r2), "=r"(r3) : "r"(addr));
}
__device__ __forceinline__ void mma_bf16(float* d, const uint32_t* a, const uint32_t* b) {
    asm volatile(
        "mma.sync.aligned.m16n8k16.row.col.f32.bf16.bf16.f32 "
        "{%0,%1,%2,%3}, {%4,%5,%6,%7}, {%8,%9}, {%0,%1,%2,%3};"
        : "+f"(d[0]), "+f"(d[1]), "+f"(d[2]), "+f"(d[3])
        : "r"(a[0]), "r"(a[1]), "r"(a[2]), "r"(a[3]), "r"(b[0]), "r"(b[1]));
}
__device__ __forceinline__ void cp_async16(uint32_t saddr, const void* gptr) {
    asm volatile("cp.async.cg.shared.global [%0], [%1], 16;"
                 :: "r"(saddr), "l"(gptr) : "memory");
}
#define CP_COMMIT() asm volatile("cp.async.commit_group;" ::: "memory")
#define CP_WAIT0()  asm volatile("cp.async.wait_group 0;" ::: "memory")

// ---------------------------------------------------------------------------
// Prepack W -> g_Wmma: bf16 hi/lo, [n][k] rows (256B), XOR-swizzled 16B chunks
// ---------------------------------------------------------------------------
__global__ __launch_bounds__(256) void prepack_kernel(
    const float* __restrict__ W_v, const float* __restrict__ W_a)
{
    const int idx = blockIdx.x * 256 + threadIdx.x;
    if (idx >= 4 * 2 * 128 * 128) return;
    const int tile = idx >> 15;
    const int seg  = (idx >> 14) & 1;
    const int rem  = idx & 16383;
    const int n    = rem >> 7;
    const int k    = rem & 127;
    const int mat  = tile >> 1;
    const int typ  = tile & 1;

    const float* Wp = (mat ? W_a : W_v) + typ * DIM * DIM;
    const float w = Wp[k * DIM + n];
    __nv_bfloat16 hi = __float2bfloat16_rn(w);
    unsigned short out;
    if (seg == 0) {
        out = *(unsigned short*)&hi;
    } else {
        __nv_bfloat16 lo = __float2bfloat16_rn(w - __bfloat162float(hi));
        out = *(unsigned short*)&lo;
    }
    const uint32_t boff = SW_OFF(n, k >> 3) + (k & 7) * 2;
    g_Wmma[tile][seg * 16384 + (boff >> 1)] = out;
}

// ---------------------------------------------------------------------------
// Persistent typed tensor-core GEMM, 256 threads (8 warps, 32x64 warp tiles).
// SMEM: Xstage raw fp32 (64K) | Xhi (32K) | Xlo (32K) | Whi (32K) | Wlo (32K).
// cp.async pipelines the NEXT tile's X into Xstage while MMA runs (no regs).
// W for the CURRENT type only; reloaded on (rare) type change — ntype sorted.
// ---------------------------------------------------------------------------
__global__ __launch_bounds__(256) void gemm_mma_kernel(
    const float* __restrict__ X, int mat,
    const int* __restrict__ ntype, float* __restrict__ Y, int N)
{
    extern __shared__ char dsm[];
    const uint32_t sbase = smem_u32(dsm);
    const uint32_t XS = 0, XH = 65536, XL = 98304, WH = 131072, WL = 163840;

    const int tid  = threadIdx.x;
    const int wid  = tid >> 5;
    const int lane = tid & 31;

    // warp tile position (4m x 2n grid of 32x64 warp tiles)
    const int m0 = (wid >> 1) * 32;
    const int n0 = (wid & 1) * 64;

    // loader mapping: row = tid>>1, half = tid&1 (64 floats = 256B each)
    const int lrow  = tid >> 1;
    const int lhalf = tid & 1;
    const uint32_t stage_sp = sbase + XS + (uint32_t)lrow * 512u + lhalf * 256u;

    int cur_wt = -1;   // type currently resident in W smem

    // ---- prologue: cp.async first tile's X into stage ---------------------
    int tile = blockIdx.x;
    if (tile < NTILES) {
        const int grow = min(tile * 128 + lrow, N - 1);   // clamp: masked later
        const char* gp = (const char*)(X + (size_t)grow * DIM + lhalf * 64);
        #pragma unroll
        for (int q = 0; q < 16; q++) cp_async16(stage_sp + q * 16, gp + q * 16);
        CP_COMMIT();
    }

    while (tile < NTILES) {
        const int row0 = tile * 128;
        const int lastRow = (row0 + 127 < N) ? (row0 + 127) : (N - 1);
        const int t0 = ntype[row0];
        const int t1 = ntype[lastRow];
        const bool mixed = (t0 != t1);
        const int ntile = tile + gridDim.x;

        CP_WAIT0();
        __syncthreads();   // stage complete + previous tile's mma done

        // ---- convert staged fp32 -> bf16 hi/lo swizzled SMEM --------------
        {
            const int kh = lhalf * 8;  // 16B-chunk base
            const float4* sp = (const float4*)(dsm + XS + lrow * 512 + lhalf * 256);
            #pragma unroll
            for (int q = 0; q < 8; q++) {
                float4 f0 = sp[2 * q], f1 = sp[2 * q + 1];
                __nv_bfloat162 h0 = __floats2bfloat162_rn(f0.x, f0.y);
                __nv_bfloat162 h1 = __floats2bfloat162_rn(f0.z, f0.w);
                __nv_bfloat162 h2 = __floats2bfloat162_rn(f1.x, f1.y);
                __nv_bfloat162 h3 = __floats2bfloat162_rn(f1.z, f1.w);
                float2 e0 = __bfloat1622float2(h0), e1 = __bfloat1622float2(h1);
                float2 e2 = __bfloat1622float2(h2), e3 = __bfloat1622float2(h3);
                __nv_bfloat162 l0 = __floats2bfloat162_rn(f0.x - e0.x, f0.y - e0.y);
                __nv_bfloat162 l1 = __floats2bfloat162_rn(f0.z - e1.x, f0.w - e1.y);
                __nv_bfloat162 l2 = __floats2bfloat162_rn(f1.x - e2.x, f1.y - e2.y);
                __nv_bfloat162 l3 = __floats2bfloat162_rn(f1.z - e3.x, f1.w - e3.y);
                const uint32_t off = SW_OFF(lrow, kh + q);
                uint4 hv, lv;
                hv.x = *(uint32_t*)&h0; hv.y = *(uint32_t*)&h1;
                hv.z = *(uint32_t*)&h2; hv.w = *(uint32_t*)&h3;
                lv.x = *(uint32_t*)&l0; lv.y = *(uint32_t*)&l1;
                lv.z = *(uint32_t*)&l2; lv.w = *(uint32_t*)&l3;
                *(uint4*)(dsm + XH + off) = hv;
                *(uint4*)(dsm + XL + off) = lv;
            }
        }
        __syncthreads();   // hi/lo ready; all stage reads done

        // ---- cp.async NEXT tile's X into stage (overlaps MMA) -------------
        if (ntile < NTILES) {
            const int grow = min(ntile * 128 + lrow, N - 1);
            const char* gp = (const char*)(X + (size_t)grow * DIM + lhalf * 64);
            #pragma unroll
            for (int q = 0; q < 16; q++) cp_async16(stage_sp + q * 16, gp + q * 16);
            CP_COMMIT();
        }

        for (int t = t0; t <= t1; ++t) {
            // ---- (re)load W for this type if not resident -----------------
            if (t != cur_wt) {
                __syncthreads();   // prior mma reads of W done
                const uint4* srcW = (const uint4*)g_Wmma[mat * 2 + t];
                uint4* dstW = (uint4*)(dsm + WH);
                #pragma unroll
                for (int i = 0; i < 16; i++)
                    dstW[tid + 256 * i] = srcW[tid + 256 * i];
                cur_wt = t;
                __syncthreads();
            }
            const uint32_t bhi = sbase + WH;
            const uint32_t blo = sbase + WL;

            float acc[2][8][4];
            #pragma unroll
            for (int i = 0; i < 2; i++)
                #pragma unroll
                for (int j = 0; j < 8; j++)
                    #pragma unroll
                    for (int p = 0; p < 4; p++) acc[i][j][p] = 0.f;

            #pragma unroll
            for (int ks = 0; ks < 8; ks++) {
                // ---- A fragments (hi & lo) --------------------------------
                uint32_t ah[2][4], al[2][4];
                {
                    const int r    = lane & 7;
                    const int half = (lane >> 3) & 1;
                    const int ksel = lane >> 4;
                    const int akc  = ks * 2 + ksel;
                    #pragma unroll
                    for (int mt = 0; mt < 2; mt++) {
                        const uint32_t aoff = SW_OFF(m0 + mt * 16 + half * 8 + r, akc);
                        ldsm_x4(ah[mt][0], ah[mt][1], ah[mt][2], ah[mt][3],
                                sbase + XH + aoff);
                        ldsm_x4(al[mt][0], al[mt][1], al[mt][2], al[mt][3],
                                sbase + XL + aoff);
                    }
                }
                // ---- B fragments (hi & lo), 64 cols -----------------------
                uint32_t bh[8][2], bl[8][2];
                {
                    const int r    = lane & 7;
                    const int ksel = (lane >> 3) & 1;
                    const int jsel = lane >> 4;
                    const int bkc  = ks * 2 + ksel;
                    #pragma unroll
                    for (int jj = 0; jj < 4; jj++) {
                        const uint32_t boff = SW_OFF(n0 + jj * 16 + jsel * 8 + r, bkc);
                        uint32_t r0, r1, r2, r3;
                        ldsm_x4(r0, r1, r2, r3, bhi + boff);
                        bh[2 * jj][0] = r0;     bh[2 * jj][1] = r1;
                        bh[2 * jj + 1][0] = r2; bh[2 * jj + 1][1] = r3;
                        ldsm_x4(r0, r1, r2, r3, blo + boff);
                        bl[2 * jj][0] = r0;     bl[2 * jj][1] = r1;
                        bl[2 * jj + 1][0] = r2; bl[2 * jj + 1][1] = r3;
                    }
                }
                // ---- 3 MMA combos from registers --------------------------
                #pragma unroll
                for (int mt = 0; mt < 2; mt++)
                    #pragma unroll
                    for (int nt = 0; nt < 8; nt++) {
                        mma_bf16(acc[mt][nt], ah[mt], bh[nt]);
                        mma_bf16(acc[mt][nt], al[mt], bh[nt]);
                        mma_bf16(acc[mt][nt], ah[mt], bl[nt]);
                    }
            }

            // ---- epilogue: masked writeout --------------------------------
            {
                const int g  = lane >> 2;
                const int c2 = (lane & 3) * 2;
                #pragma unroll
                for (int mt = 0; mt < 2; mt++) {
                    #pragma unroll
                    for (int half = 0; half < 2; half++) {
                        const int grow = row0 + m0 + mt * 16 + half * 8 + g;
                        if (grow < N && (!mixed || ntype[grow] == t)) {
                            float2* yp = (float2*)(Y + (size_t)grow * DIM + n0 + c2);
                            #pragma unroll
                            for (int nt = 0; nt < 8; nt++)
                                yp[nt * 4] = make_float2(acc[mt][nt][half * 2],
                                                         acc[mt][nt][half * 2 + 1]);
                        }
                    }
                }
            }
        }

        tile = ntile;
    }
}

// ---------------------------------------------------------------------------
// Edge scatter-sum: g_h[dst[e],:] += g_v[src[e],:]. 8 edges per warp:
// uniform int4 index loads, 8 independent gathers (MLP=8), 8 RED.128/lane.
// (At the LTS traffic cap ~74us — leave as is.)
// ---------------------------------------------------------------------------
__global__ __launch_bounds__(256) void scatter_kernel(
    const int* __restrict__ src, const int* __restrict__ dst)
{
    const int w    = (int)((blockIdx.x * (unsigned)blockDim.x + threadIdx.x) >> 5);
    const int lane = threadIdx.x & 31;
    const int4 s0 = __ldg((const int4*)src + w * 2);
    const int4 s1 = __ldg((const int4*)src + w * 2 + 1);
    const int4 d0 = __ldg((const int4*)dst + w * 2);
    const int4 d1 = __ldg((const int4*)dst + w * 2 + 1);
    const int s[8] = {s0.x, s0.y, s0.z, s0.w, s1.x, s1.y, s1.z, s1.w};
    const int d[8] = {d0.x, d0.y, d0.z, d0.w, d1.x, d1.y, d1.z, d1.w};

    float4 x[8];
    #pragma unroll
    for (int i = 0; i < 8; i++)
        x[i] = ((const float4*)(g_v + (size_t)s[i] * DIM))[lane];

    #pragma unroll
    for (int i = 0; i < 8; i++) {
        float* hd = g_h + (size_t)d[i] * DIM + lane * 4;
        asm volatile("red.global.add.v4.f32 [%0], {%1, %2, %3, %4};"
                     :: "l"(hd), "f"(x[i].x), "f"(x[i].y), "f"(x[i].z), "f"(x[i].w)
                     : "memory");
    }
}

// ---------------------------------------------------------------------------
__global__ __launch_bounds__(256) void zero_h_kernel()
{
    const int i = blockIdx.x * blockDim.x + threadIdx.x;
    if (i < N_NODES * DIM / 4)
        ((float4*)g_h)[i] = make_float4(0.f, 0.f, 0.f, 0.f);
}

// ---------------------------------------------------------------------------
extern "C" void kernel_launch(void* const* d_in, const int* in_sizes, int n_in,
                              void* d_out, int out_size)
{
    const float* x     = (const float*)d_in[0];
    const int*   ntype = (const int*)  d_in[1];
    const int*   src   = (const int*)  d_in[2];
    const int*   dst   = (const int*)  d_in[3];
    const float* W_v   = (const float*)d_in[4];
    const float* W_a   = (const float*)d_in[5];
    float*       out   = (float*)d_out;

    float *v_ptr, *h_ptr;
    cudaGetSymbolAddress((void**)&v_ptr, g_v);
    cudaGetSymbolAddress((void**)&h_ptr, g_h);

    const int N = N_NODES;
    const int SMEM_DYN = 196608;   // Xstage 64K + Xhi/Xlo 64K + W 64K
    cudaFuncSetAttribute(gemm_mma_kernel,
                         cudaFuncAttributeMaxDynamicSharedMemorySize, SMEM_DYN);

    // prepack W (bf16 hi/lo swizzled SMEM images)
    prepack_kernel<<<(4 * 2 * 128 * 128 + 255) / 256, 256>>>(W_v, W_a);
    // h = 0
    zero_h_kernel<<<(N_NODES * DIM / 4 + 255) / 256, 256>>>();
    // v = typed_linear(x, W_v, ntype)
    gemm_mma_kernel<<<148, 256, SMEM_DYN>>>(x, 0, ntype, v_ptr, N);
    // h[dst] += v[src]  (8 edges/warp)
    scatter_kernel<<<N_EDGES / 8 / 8, 256>>>(src, dst);
    // out = typed_linear(h, W_a, ntype)
    gemm_mma_kernel<<<148, 256, SMEM_DYN>>>(h_ptr, 1, ntype, out, N);
}

// round 11
// speedup vs baseline: 1.2095x; 1.2095x over previous
#include <cuda_runtime.h>
#include <cuda_bf16.h>
#include <cstdint>

#define N_NODES 100000
#define N_EDGES 800000
#define DIM 128
#define NTILES ((N_NODES + 127) / 128)

// ---------------------------------------------------------------------------
// Scratch (allocation-free rule: __device__ globals)
// ---------------------------------------------------------------------------
__device__ float g_v[N_NODES * DIM];
__device__ float g_h[N_NODES * DIM];
__device__ unsigned short g_Wmma[4][2 * 128 * 128];  // prepacked W images

// swizzled byte offset of (row, 16B-chunk kc) in a 256B-row tile
#define SW_OFF(row, kc) ((uint32_t)(row) * 256u + ((uint32_t)(((kc) ^ ((row) & 7))) << 4))

__device__ __forceinline__ uint32_t smem_u32(const void* p) {
    uint32_t a;
    asm("{ .reg .u64 t; cvta.to.shared.u64 t, %1; cvt.u32.u64 %0, t; }"
        : "=r"(a) : "l"(p));
    return a;
}
__device__ __forceinline__ void ldsm_x4(uint32_t& r0, uint32_t& r1, uint32_t& r2,
                                        uint32_t& r3, uint32_t addr) {
    asm volatile("ldmatrix.sync.aligned.m8n8.x4.shared.b16 {%0,%1,%2,%3}, [%4];"
                 : "=r"(r0), "=r"(r1), "=r"(r2), "=r"(r3) : "r"(addr));
}
__device__ __forceinline__ void mma_bf16(float* d, const uint32_t* a, const uint32_t* b) {
    asm volatile(
        "mma.sync.aligned.m16n8k16.row.col.f32.bf16.bf16.f32 "
        "{%0,%1,%2,%3}, {%4,%5,%6,%7}, {%8,%9}, {%0,%1,%2,%3};"
        : "+f"(d[0]), "+f"(d[1]), "+f"(d[2]), "+f"(d[3])
        : "r"(a[0]), "r"(a[1]), "r"(a[2]), "r"(a[3]), "r"(b[0]), "r"(b[1]));
}

// ---------------------------------------------------------------------------
// Prepack W -> g_Wmma: bf16 hi/lo, [n][k] rows (256B), XOR-swizzled 16B chunks
// ---------------------------------------------------------------------------
__global__ __launch_bounds__(256) void prepack_kernel(
    const float* __restrict__ W_v, const float* __restrict__ W_a)
{
    const int idx = blockIdx.x * 256 + threadIdx.x;
    if (idx >= 4 * 2 * 128 * 128) return;
    const int tile = idx >> 15;
    const int seg  = (idx >> 14) & 1;
    const int rem  = idx & 16383;
    const int n    = rem >> 7;
    const int k    = rem & 127;
    const int mat  = tile >> 1;
    const int typ  = tile & 1;

    const float* Wp = (mat ? W_a : W_v) + typ * DIM * DIM;
    const float w = Wp[k * DIM + n];
    __nv_bfloat16 hi = __float2bfloat16_rn(w);
    unsigned short out;
    if (seg == 0) {
        out = *(unsigned short*)&hi;
    } else {
        __nv_bfloat16 lo = __float2bfloat16_rn(w - __bfloat162float(hi));
        out = *(unsigned short*)&lo;
    }
    const uint32_t boff = SW_OFF(n, k >> 3) + (k & 7) * 2;
    g_Wmma[tile][seg * 16384 + (boff >> 1)] = out;
}

// ---------------------------------------------------------------------------
// Persistent typed tensor-core GEMM (round-6 config): Y = X @ W[ntype]
// 256 threads (8 warps, 4m x 2n grid of 32x64 warp tiles). W (both types,
// hi/lo = 128KB) resident in SMEM; register prefetch of next tile's X.
// do_zero: gemm1 additionally zeroes g_h with fire-and-forget stores that
// drain behind the compute phase (replaces the standalone zero kernel).
// ---------------------------------------------------------------------------
__global__ __launch_bounds__(256) void gemm_mma_kernel(
    const float* __restrict__ X, int mat, int do_zero,
    const int* __restrict__ ntype, float* __restrict__ Y, int N)
{
    extern __shared__ char dsm[];
    const uint32_t sbase = smem_u32(dsm);
    const uint32_t XH = 0, XL = 32768, WB = 65536;   // W: +type*65536 +seg*32768

    const int tid  = threadIdx.x;
    const int wid  = tid >> 5;
    const int lane = tid & 31;

    // ---- fire-and-forget zero of g_h (gemm1 only) -------------------------
    if (do_zero) {
        float4* hp = (float4*)g_h;
        const int total  = N_NODES * DIM / 4;
        const int stride = gridDim.x * 256;
        for (int i = blockIdx.x * 256 + tid; i < total; i += stride)
            hp[i] = make_float4(0.f, 0.f, 0.f, 0.f);
    }

    // ---- load W (both types, hi+lo = 128KB) once -------------------------
    {
        const uint4* srcW0 = (const uint4*)g_Wmma[mat * 2 + 0];
        const uint4* srcW1 = (const uint4*)g_Wmma[mat * 2 + 1];
        uint4* dstW0 = (uint4*)(dsm + WB);
        uint4* dstW1 = (uint4*)(dsm + WB + 65536);
        #pragma unroll
        for (int i = 0; i < 16; i++) {
            dstW0[tid + 256 * i] = srcW0[tid + 256 * i];
            dstW1[tid + 256 * i] = srcW1[tid + 256 * i];
        }
    }

    const int m0 = (wid >> 1) * 32;
    const int n0 = (wid & 1) * 64;
    const int lrow  = tid >> 1;
    const int lkoff = (tid & 1) * 64;

    float4 pf[16];
    int tile = blockIdx.x;
    {
        const int grow = tile * 128 + lrow;
        if (tile < NTILES && grow < N) {
            const float4* xp = (const float4*)(X + (size_t)grow * DIM + lkoff);
            #pragma unroll
            for (int q = 0; q < 16; q++) pf[q] = xp[q];
        } else {
            #pragma unroll
            for (int q = 0; q < 16; q++) pf[q] = make_float4(0, 0, 0, 0);
        }
    }

    while (tile < NTILES) {
        const int row0 = tile * 128;
        const int lastRow = (row0 + 127 < N) ? (row0 + 127) : (N - 1);
        const int t0 = ntype[row0];
        const int t1 = ntype[lastRow];
        const bool mixed = (t0 != t1);
        const int ntile = tile + gridDim.x;

        __syncthreads();   // previous tile's compute done before X overwrite

        // ---- convert prefetched X -> bf16 hi/lo swizzled SMEM -------------
        {
            const int kh = (tid & 1) * 8;
            #pragma unroll
            for (int q = 0; q < 8; q++) {
                float4 f0 = pf[2 * q], f1 = pf[2 * q + 1];
                __nv_bfloat162 h0 = __floats2bfloat162_rn(f0.x, f0.y);
                __nv_bfloat162 h1 = __floats2bfloat162_rn(f0.z, f0.w);
                __nv_bfloat162 h2 = __floats2bfloat162_rn(f1.x, f1.y);
                __nv_bfloat162 h3 = __floats2bfloat162_rn(f1.z, f1.w);
                float2 e0 = __bfloat1622float2(h0), e1 = __bfloat1622float2(h1);
                float2 e2 = __bfloat1622float2(h2), e3 = __bfloat1622float2(h3);
                __nv_bfloat162 l0 = __floats2bfloat162_rn(f0.x - e0.x, f0.y - e0.y);
                __nv_bfloat162 l1 = __floats2bfloat162_rn(f0.z - e1.x, f0.w - e1.y);
                __nv_bfloat162 l2 = __floats2bfloat162_rn(f1.x - e2.x, f1.y - e2.y);
                __nv_bfloat162 l3 = __floats2bfloat162_rn(f1.z - e3.x, f1.w - e3.y);
                const uint32_t off = SW_OFF(lrow, kh + q);
                uint4 hv, lv;
                hv.x = *(uint32_t*)&h0; hv.y = *(uint32_t*)&h1;
                hv.z = *(uint32_t*)&h2; hv.w = *(uint32_t*)&h3;
                lv.x = *(uint32_t*)&l0; lv.y = *(uint32_t*)&l1;
                lv.z = *(uint32_t*)&l2; lv.w = *(uint32_t*)&l3;
                *(uint4*)(dsm + XH + off) = hv;
                *(uint4*)(dsm + XL + off) = lv;
            }
        }

        // ---- prefetch next tile's X (latency hidden behind MMA) ----------
        {
            const int grow = ntile * 128 + lrow;
            if (ntile < NTILES && grow < N) {
                const float4* xp = (const float4*)(X + (size_t)grow * DIM + lkoff);
                #pragma unroll
                for (int q = 0; q < 16; q++) pf[q] = xp[q];
            } else {
                #pragma unroll
                for (int q = 0; q < 16; q++) pf[q] = make_float4(0, 0, 0, 0);
            }
        }
        __syncthreads();

        for (int t = t0; t <= t1; ++t) {
            const uint32_t bhi = sbase + WB + (uint32_t)t * 65536u;
            const uint32_t blo = bhi + 32768u;

            float acc[2][8][4];
            #pragma unroll
            for (int i = 0; i < 2; i++)
                #pragma unroll
                for (int j = 0; j < 8; j++)
                    #pragma unroll
                    for (int p = 0; p < 4; p++) acc[i][j][p] = 0.f;

            #pragma unroll
            for (int ks = 0; ks < 8; ks++) {
                uint32_t ah[2][4], al[2][4];
                {
                    const int r    = lane & 7;
                    const int half = (lane >> 3) & 1;
                    const int ksel = lane >> 4;
                    const int akc  = ks * 2 + ksel;
                    #pragma unroll
                    for (int mt = 0; mt < 2; mt++) {
                        const uint32_t aoff = SW_OFF(m0 + mt * 16 + half * 8 + r, akc);
                        ldsm_x4(ah[mt][0], ah[mt][1], ah[mt][2], ah[mt][3],
                                sbase + XH + aoff);
                        ldsm_x4(al[mt][0], al[mt][1], al[mt][2], al[mt][3],
                                sbase + XL + aoff);
                    }
                }
                uint32_t bh[8][2], bl[8][2];
                {
                    const int r    = lane & 7;
                    const int ksel = (lane >> 3) & 1;
                    const int jsel = lane >> 4;
                    const int bkc  = ks * 2 + ksel;
                    #pragma unroll
                    for (int jj = 0; jj < 4; jj++) {
                        const uint32_t boff = SW_OFF(n0 + jj * 16 + jsel * 8 + r, bkc);
                        uint32_t r0, r1, r2, r3;
                        ldsm_x4(r0, r1, r2, r3, bhi + boff);
                        bh[2 * jj][0] = r0;     bh[2 * jj][1] = r1;
                        bh[2 * jj + 1][0] = r2; bh[2 * jj + 1][1] = r3;
                        ldsm_x4(r0, r1, r2, r3, blo + boff);
                        bl[2 * jj][0] = r0;     bl[2 * jj][1] = r1;
                        bl[2 * jj + 1][0] = r2; bl[2 * jj + 1][1] = r3;
                    }
                }
                #pragma unroll
                for (int mt = 0; mt < 2; mt++)
                    #pragma unroll
                    for (int nt = 0; nt < 8; nt++) {
                        mma_bf16(acc[mt][nt], ah[mt], bh[nt]);
                        mma_bf16(acc[mt][nt], al[mt], bh[nt]);
                        mma_bf16(acc[mt][nt], ah[mt], bl[nt]);
                    }
            }

            {
                const int g  = lane >> 2;
                const int c2 = (lane & 3) * 2;
                #pragma unroll
                for (int mt = 0; mt < 2; mt++) {
                    #pragma unroll
                    for (int half = 0; half < 2; half++) {
                        const int grow = row0 + m0 + mt * 16 + half * 8 + g;
                        if (grow < N && (!mixed || ntype[grow] == t)) {
                            float2* yp = (float2*)(Y + (size_t)grow * DIM + n0 + c2);
                            #pragma unroll
                            for (int nt = 0; nt < 8; nt++)
                                yp[nt * 4] = make_float2(acc[mt][nt][half * 2],
                                                         acc[mt][nt][half * 2 + 1]);
                        }
                    }
                }
            }
        }

        tile = ntile;
    }
}

// ---------------------------------------------------------------------------
// Edge scatter-sum: g_h[dst[e],:] += g_v[src[e],:]. 8 edges per warp:
// uniform int4 index loads, 8 independent gathers (MLP=8), 8 RED.128/lane.
// (At the LTS traffic cap ~73us.)
// ---------------------------------------------------------------------------
__global__ __launch_bounds__(256) void scatter_kernel(
    const int* __restrict__ src, const int* __restrict__ dst)
{
    const int w    = (int)((blockIdx.x * (unsigned)blockDim.x + threadIdx.x) >> 5);
    const int lane = threadIdx.x & 31;
    const int4 s0 = __ldg((const int4*)src + w * 2);
    const int4 s1 = __ldg((const int4*)src + w * 2 + 1);
    const int4 d0 = __ldg((const int4*)dst + w * 2);
    const int4 d1 = __ldg((const int4*)dst + w * 2 + 1);
    const int s[8] = {s0.x, s0.y, s0.z, s0.w, s1.x, s1.y, s1.z, s1.w};
    const int d[8] = {d0.x, d0.y, d0.z, d0.w, d1.x, d1.y, d1.z, d1.w};

    float4 x[8];
    #pragma unroll
    for (int i = 0; i < 8; i++)
        x[i] = ((const float4*)(g_v + (size_t)s[i] * DIM))[lane];

    #pragma unroll
    for (int i = 0; i < 8; i++) {
        float* hd = g_h + (size_t)d[i] * DIM + lane * 4;
        asm volatile("red.global.add.v4.f32 [%0], {%1, %2, %3, %4};"
                     :: "l"(hd), "f"(x[i].x), "f"(x[i].y), "f"(x[i].z), "f"(x[i].w)
                     : "memory");
    }
}

// ---------------------------------------------------------------------------
extern "C" void kernel_launch(void* const* d_in, const int* in_sizes, int n_in,
                              void* d_out, int out_size)
{
    const float* x     = (const float*)d_in[0];
    const int*   ntype = (const int*)  d_in[1];
    const int*   src   = (const int*)  d_in[2];
    const int*   dst   = (const int*)  d_in[3];
    const float* W_v   = (const float*)d_in[4];
    const float* W_a   = (const float*)d_in[5];
    float*       out   = (float*)d_out;

    float *v_ptr, *h_ptr;
    cudaGetSymbolAddress((void**)&v_ptr, g_v);
    cudaGetSymbolAddress((void**)&h_ptr, g_h);

    const int N = N_NODES;
    const int SMEM_DYN = 196608;   // Xhi+Xlo (64K) + W both types hi/lo (128K)
    cudaFuncSetAttribute(gemm_mma_kernel,
                         cudaFuncAttributeMaxDynamicSharedMemorySize, SMEM_DYN);

    // prepack W (bf16 hi/lo swizzled SMEM images)
    prepack_kernel<<<(4 * 2 * 128 * 128 + 255) / 256, 256>>>(W_v, W_a);
    // v = typed_linear(x, W_v, ntype)  + fire-and-forget zero of g_h
    gemm_mma_kernel<<<148, 256, SMEM_DYN>>>(x, 0, 1, ntype, v_ptr, N);
    // h[dst] += v[src]  (8 edges/warp)
    scatter_kernel<<<N_EDGES / 8 / 8, 256>>>(src, dst);
    // out = typed_linear(h, W_a, ntype)
    gemm_mma_kernel<<<148, 256, SMEM_DYN>>>(h_ptr, 1, 0, ntype, out, N);
}